// round 13
// baseline (speedup 1.0000x reference)
#include <cuda_runtime.h>

// Problem constants (fixed by the reference)
#define BB 8
#define SS 8192
#define DD 768
#define VV 64
#define LL 26
#define NSEG (BB * VV)      // 512
#define NGRP 2              // gather groups per CTA
#define NTHR (NGRP * 192)   // 384 threads = 12 warps
#define NW   (NTHR / 32)    // 12 warps
#define WSUB 768            // per-warp sublist: absolute worst case (ids/warp)
#define CAP  2048           // compacted list capacity (cnt ~ 128 +/- 11)

// Single kernel, one CTA per (batch, symbol) segment.
//  A: ATOMIC-FREE id scan: each warp ballots matches over its int4 chunks and
//     appends to a private sublist via popc-prefix (no ATOMS serialization),
//     then sublists are compacted into one contiguous slist.
//  B: 2 groups of 192 lanes gather-sum matching rows (float4, unroll-8).
//  C: reduce partials, mean + 26-label head, masked write.
__global__ __launch_bounds__(NTHR, 4) void k_fused(
    const float* __restrict__ h,      // [B*S, D]
    const int*   __restrict__ ids,    // [B*S]
    const float* __restrict__ Wm,     // [L, D]
    const float* __restrict__ bias,   // [L]
    float* __restrict__ out)          // [B, V, L]
{
    const int seg   = blockIdx.x;
    const int b     = seg >> 6;
    const int v     = seg & (VV - 1);
    const int tid   = threadIdx.x;
    const int grp   = tid / 192;       // 0..1
    const int lane4 = tid % 192;       // float4 column within D
    const int warp  = tid >> 5;        // 0..11
    const int lane  = tid & 31;

    __shared__ __align__(16) float ssum[NGRP][DD];   // 6 KB
    __shared__ int sub[NW][WSUB];                    // 36 KB per-warp lists
    __shared__ int slist[CAP];                       // 8 KB compacted
    __shared__ int wcnt[NW];
    __shared__ int woff[NW + 1];

    // Masked symbol 0: write zeros, leave.
    if (v == 0) {
        if (tid < LL) out[seg * LL + tid] = 0.0f;
        return;
    }

    // ---- Phase A: atomic-free warp-ballot scan ----
    {
        const int4* __restrict__ idb4 = (const int4*)(ids + b * SS);
        const unsigned below = (1u << lane) - 1u;
        int wbase = 0;                 // per-warp running count (replicated)
        #pragma unroll
        for (int g = 0; g < 6; ++g) {
            const int q = tid + g * NTHR;           // int4 index
            const bool valid = (q < SS / 4);
            int4 w4 = make_int4(-1, -1, -1, -1);
            if (valid) w4 = __ldg(&idb4[q]);
            const int s = q * 4;
            unsigned bal;
            bool m;
            m = (w4.x == v); bal = __ballot_sync(0xffffffffu, m);
            if (m) sub[warp][wbase + __popc(bal & below)] = s + 0;
            wbase += __popc(bal);
            m = (w4.y == v); bal = __ballot_sync(0xffffffffu, m);
            if (m) sub[warp][wbase + __popc(bal & below)] = s + 1;
            wbase += __popc(bal);
            m = (w4.z == v); bal = __ballot_sync(0xffffffffu, m);
            if (m) sub[warp][wbase + __popc(bal & below)] = s + 2;
            wbase += __popc(bal);
            m = (w4.w == v); bal = __ballot_sync(0xffffffffu, m);
            if (m) sub[warp][wbase + __popc(bal & below)] = s + 3;
            wbase += __popc(bal);
        }
        if (lane == 0) wcnt[warp] = wbase;
    }
    __syncthreads();

    // Prefix over 12 warp counts (thread 0; trivial).
    if (tid == 0) {
        int o = 0;
        #pragma unroll
        for (int w = 0; w < NW; ++w) { woff[w] = o; o += wcnt[w]; }
        woff[NW] = o;
    }
    __syncthreads();

    // Compact sublists into slist (each warp copies its own, lane-strided).
    {
        const int o = woff[warp];
        const int n = wcnt[warp];
        for (int j = lane; j < n; j += 32) {
            const int p = o + j;
            if (p < CAP) slist[p] = sub[warp][j];
        }
    }
    __syncthreads();
    const int cnt = (woff[NW] < CAP) ? woff[NW] : CAP;

    // ---- Phase B: group g sums tokens g, g+2, ... (unroll-8) ----
    float4 acc = make_float4(0.f, 0.f, 0.f, 0.f);
    {
        const float4* __restrict__ hb = (const float4*)h + (long)b * SS * (DD / 4);
        int i = grp;
        for (; i + 7 * NGRP < cnt; i += 8 * NGRP) {
            float4 t0 = __ldg(&hb[(long)slist[i + 0 * NGRP] * (DD / 4) + lane4]);
            float4 t1 = __ldg(&hb[(long)slist[i + 1 * NGRP] * (DD / 4) + lane4]);
            float4 t2 = __ldg(&hb[(long)slist[i + 2 * NGRP] * (DD / 4) + lane4]);
            float4 t3 = __ldg(&hb[(long)slist[i + 3 * NGRP] * (DD / 4) + lane4]);
            float4 t4 = __ldg(&hb[(long)slist[i + 4 * NGRP] * (DD / 4) + lane4]);
            float4 t5 = __ldg(&hb[(long)slist[i + 5 * NGRP] * (DD / 4) + lane4]);
            float4 t6 = __ldg(&hb[(long)slist[i + 6 * NGRP] * (DD / 4) + lane4]);
            float4 t7 = __ldg(&hb[(long)slist[i + 7 * NGRP] * (DD / 4) + lane4]);
            acc.x += ((t0.x + t1.x) + (t2.x + t3.x)) + ((t4.x + t5.x) + (t6.x + t7.x));
            acc.y += ((t0.y + t1.y) + (t2.y + t3.y)) + ((t4.y + t5.y) + (t6.y + t7.y));
            acc.z += ((t0.z + t1.z) + (t2.z + t3.z)) + ((t4.z + t5.z) + (t6.z + t7.z));
            acc.w += ((t0.w + t1.w) + (t2.w + t3.w)) + ((t4.w + t5.w) + (t6.w + t7.w));
        }
        for (; i < cnt; i += NGRP) {
            float4 t = __ldg(&hb[(long)slist[i] * (DD / 4) + lane4]);
            acc.x += t.x; acc.y += t.y; acc.z += t.z; acc.w += t.w;
        }
    }
    ((float4*)ssum[grp])[lane4] = acc;
    __syncthreads();

    // ---- Phase C1: reduce the 2 group partials into ssum[0] ----
    if (tid < 192) {
        float4 a0 = ((const float4*)ssum[0])[tid];
        float4 a1 = ((const float4*)ssum[1])[tid];
        a0.x += a1.x; a0.y += a1.y; a0.z += a1.z; a0.w += a1.w;
        ((float4*)ssum[0])[tid] = a0;
    }
    __syncthreads();

    // ---- Phase C2: mean + linear head (12 warps over 26 labels) ----
    const bool  active = (cnt > 0);
    const float inv    = 1.0f / (float)(cnt > 0 ? cnt : 1);

    for (int l = warp; l < LL; l += NW) {
        float s = 0.f;
        #pragma unroll
        for (int k = lane; k < DD; k += 32)
            s += ssum[0][k] * __ldg(&Wm[l * DD + k]);
        #pragma unroll
        for (int o = 16; o; o >>= 1)
            s += __shfl_xor_sync(0xffffffffu, s, o);
        if (lane == 0)
            out[seg * LL + l] = active ? (s * inv + __ldg(&bias[l])) : 0.0f;
    }
}

// ---------------------------------------------------------------------------
extern "C" void kernel_launch(void* const* d_in, const int* in_sizes, int n_in,
                              void* d_out, int out_size) {
    const float* h    = nullptr;   // 50331648
    const float* Wm   = nullptr;   // 19968
    const float* bias = nullptr;   // 26
    const int*   ids  = nullptr;   // 65536
    for (int i = 0; i < n_in; ++i) {
        switch (in_sizes[i]) {
            case BB * SS * DD: h    = (const float*)d_in[i]; break;
            case LL * DD:      Wm   = (const float*)d_in[i]; break;
            case LL:           bias = (const float*)d_in[i]; break;
            case BB * SS:      ids  = (const int*)d_in[i];   break;
        }
    }
    float* out = (float*)d_out;

    k_fused<<<NSEG, NTHR>>>(h, ids, Wm, bias, out);
}